// round 2
// baseline (speedup 1.0000x reference)
#include <cuda_runtime.h>
#include <math.h>

// Problem constants
#define B_ 2
#define C_ 256
#define H_ 48
#define W_ 48
#define HW_ 2304          // 48*48
#define HID_ 64           // hidden = C/RATIO
#define NH_ 2
#define NG_ 2
#define C2_ 32            // hidden/NH
#define GC_ 32            // hidden/NG
#define OH_ 96
#define OW_ 96
#define N1_ 9216          // 96*96
#define KS_ 3
#define NSL_ 9            // KS*KS
#define RF_ 11.0f
#define SCALE_ 0.17677669529663689f   // 32^-0.5
#define RESC_ (47.0f/95.0f)           // (H-1)/(oH-1), align_corners

// Scratch (static device allocations; allowed)
__device__ float  g_xt   [B_ * HW_ * C_];      // x transposed NHWC  (also "v")
__device__ float  g_q48  [B_ * HW_ * HID_];    // q at 48x48, position-major
__device__ float  g_kt   [B_ * HW_ * HID_];    // k, position-major
__device__ float  g_qt   [B_ * N1_ * HID_];    // q upsampled to 96x96, position-major
__device__ float  g_tbuf [B_*NG_ * N1_ * GC_]; // offset-net hidden, position-major
__device__ float2 g_crd  [B_*NG_ * NSL_ * N1_];// sample coords (iy, ix)

// ---------------------------------------------------------------------------
// K0: transpose x [B,C,HW] -> x_t [B,HW,C]   (tiled 32x32)
__global__ void k_transpose(const float* __restrict__ x) {
    __shared__ float tile[32][33];
    int b  = blockIdx.z;
    int p0 = blockIdx.x * 32;   // HW tile
    int c0 = blockIdx.y * 32;   // C tile
    int tx = threadIdx.x, ty = threadIdx.y;   // block 32x8
    const float* xb = x + (size_t)b * C_ * HW_;
    float* xtb = g_xt + (size_t)b * HW_ * C_;
#pragma unroll
    for (int k = 0; k < 4; k++) {
        int cc = ty + k * 8;
        tile[cc][tx] = xb[(size_t)(c0 + cc) * HW_ + (p0 + tx)];
    }
    __syncthreads();
#pragma unroll
    for (int k = 0; k < 4; k++) {
        int pp = ty + k * 8;
        xtb[(size_t)(p0 + pp) * C_ + (c0 + tx)] = tile[tx][pp];
    }
}

// ---------------------------------------------------------------------------
// K1: channel LayerNorm over C=256 + q/k 1x1 convs. One block per (b,p48).
__global__ void k_ln_qk(const float* __restrict__ ln_g, const float* __restrict__ ln_b,
                        const float* __restrict__ Wq,   const float* __restrict__ Wk) {
    __shared__ float xs[256];
    __shared__ float red[256];
    int t = threadIdx.x;
    size_t pos = blockIdx.x;             // b*HW + p
    float v = g_xt[pos * C_ + t];
    red[t] = v; __syncthreads();
    for (int s = 128; s > 0; s >>= 1) { if (t < s) red[t] += red[t + s]; __syncthreads(); }
    float mean = red[0] * (1.0f / 256.0f);
    __syncthreads();
    float d = v - mean;
    red[t] = d * d; __syncthreads();
    for (int s = 128; s > 0; s >>= 1) { if (t < s) red[t] += red[t + s]; __syncthreads(); }
    float inv = rsqrtf(red[0] * (1.0f / 256.0f) + 1e-5f);
    __syncthreads();
    xs[t] = d * inv * ln_g[t] + ln_b[t];
    __syncthreads();
    // 128 outputs (64 q + 64 k), 2 threads each (split the 256-dot)
    int o = t & 127, half = t >> 7;
    const float* Wrow = (o < 64) ? (Wq + o * 256) : (Wk + (o - 64) * 256);
    float acc = 0.0f;
    int c0 = half * 128;
#pragma unroll 8
    for (int c = 0; c < 128; c++) acc += Wrow[c0 + c] * xs[c0 + c];
    red[t] = acc; __syncthreads();
    if (t < 128) {
        float s = red[t] + red[t + 128];
        if (o < 64) g_q48[pos * HID_ + o]        = s;
        else        g_kt [pos * HID_ + (o - 64)] = s;
    }
}

// ---------------------------------------------------------------------------
// K2: bilinear upsample q48 -> qt (align_corners), elementwise gather
__global__ void k_resize() {
    int idx = blockIdx.x * 256 + threadIdx.x;      // B*N1*HID = 1,179,648 exactly
    int c = idx & 63;
    int p = (idx >> 6) % N1_;
    int b = (idx >> 6) / N1_;
    int oy = p / OW_, ox = p % OW_;
    float ys = oy * RESC_;
    float xsf = ox * RESC_;
    int y0 = min(max((int)floorf(ys), 0), H_ - 2);
    int x0 = min(max((int)floorf(xsf), 0), W_ - 2);
    float wy = ys - (float)y0, wx = xsf - (float)x0;
    const float* base = g_q48 + (size_t)b * HW_ * HID_;
    float v00 = base[((y0    ) * W_ + x0    ) * HID_ + c];
    float v01 = base[((y0    ) * W_ + x0 + 1) * HID_ + c];
    float v10 = base[((y0 + 1) * W_ + x0    ) * HID_ + c];
    float v11 = base[((y0 + 1) * W_ + x0 + 1) * HID_ + c];
    g_qt[idx] = (1.f - wy) * ((1.f - wx) * v00 + wx * v01)
              +         wy * ((1.f - wx) * v10 + wx * v11);
}

// ---------------------------------------------------------------------------
// K3: offset net stage 1: depthwise 3x3 conv + channel LN(32) + exact GELU.
//     8 warps/block, one warp per (bg,p96).
__global__ void k_off1(const float* __restrict__ dw_w,
                       const float* __restrict__ og, const float* __restrict__ ob) {
    int t = threadIdx.x;
    int ch = t & 31, u = t >> 5;
    int gid = blockIdx.x * 8 + u;        // < 4*9216
    int bg = gid / N1_, p = gid % N1_;
    int b = bg >> 1, g = bg & 1;
    int y = p / OW_, x = p % OW_;
    const float* qb = g_qt + (size_t)b * N1_ * HID_ + g * GC_ + ch;
    float acc = 0.0f;
#pragma unroll
    for (int ky = 0; ky < 3; ky++) {
        int ny = y + ky - 1;
        if (ny < 0 || ny >= OH_) continue;
#pragma unroll
        for (int kx = 0; kx < 3; kx++) {
            int nx = x + kx - 1;
            if (nx < 0 || nx >= OW_) continue;
            acc += qb[(size_t)(ny * OW_ + nx) * HID_] * dw_w[ch * 9 + ky * 3 + kx];
        }
    }
    // warp LN over 32 channels
    float s = acc;
#pragma unroll
    for (int o = 16; o; o >>= 1) s += __shfl_xor_sync(0xffffffffu, s, o);
    float mean = s * (1.0f / 32.0f);
    float d = acc - mean;
    float vv = d * d;
#pragma unroll
    for (int o = 16; o; o >>= 1) vv += __shfl_xor_sync(0xffffffffu, vv, o);
    float inv = rsqrtf(vv * (1.0f / 32.0f) + 1e-5f);
    float tn = d * inv * og[ch] + ob[ch];
    float ge = 0.5f * tn * (1.0f + erff(tn * 0.70710678118654752f));
    g_tbuf[(size_t)gid * GC_ + ch] = ge;
}

// ---------------------------------------------------------------------------
// K4: offset net stage 2: 3x3 conv 32->18 + bias + tanh -> sample coords.
__global__ void k_off2(const float* __restrict__ off_w, const float* __restrict__ off_b) {
    __shared__ float sm[8][9 * GC_];
    __shared__ float pr[8][18];
    int t = threadIdx.x;
    int ch = t & 31, u = t >> 5;
    int gid = blockIdx.x * 8 + u;
    int bg = gid / N1_, p = gid % N1_;
    int y = p / OW_, x = p % OW_;
    const float* tb = g_tbuf + (size_t)bg * N1_ * GC_;
#pragma unroll
    for (int tap = 0; tap < 9; tap++) {
        int ny = y + tap / 3 - 1, nx = x + tap % 3 - 1;
        bool inb = (ny >= 0) && (ny < OH_) && (nx >= 0) && (nx < OW_);
        sm[u][tap * GC_ + ch] = inb ? tb[(size_t)(ny * OW_ + nx) * GC_ + ch] : 0.0f;
    }
    __syncwarp();
    if (ch < 18) {
        float acc = off_b[ch];
        const float* wrow = off_w + ch * (GC_ * 9);
#pragma unroll 4
        for (int ic = 0; ic < GC_; ic++) {
#pragma unroll
            for (int tap = 0; tap < 9; tap++)
                acc += sm[u][tap * GC_ + ic] * wrow[ic * 9 + tap];
        }
        pr[u][ch] = acc;
    }
    __syncwarp();
    if (ch < 9) {
        int ky = ch / 3, kx = ch % 3;
        float py = tanhf(pr[u][2 * ch    ]) * RF_ + (float)(ky - 1) + (float)y;
        float px = tanhf(pr[u][2 * ch + 1]) * RF_ + (float)(kx - 1) + (float)x;
        g_crd[((size_t)bg * NSL_ + ch) * N1_ + p] = make_float2(py * RESC_, px * RESC_);
    }
}

// ---------------------------------------------------------------------------
// K5: fused grid-sample + attention + output. One warp per (b,h,p96).
//     8 warps/block handle 8 consecutive p for one (b,h); smem-staged output.
__global__ void k_attn(const float* __restrict__ rpb, float* __restrict__ out) {
    __shared__ float so[128][9];   // [channel][warp], padded: conflict-free
    int t = threadIdx.x;
    int lane = t & 31, w = t >> 5;
    int bh = blockIdx.x / (N1_ / 8);
    int pt = blockIdx.x % (N1_ / 8);
    int b = bh >> 1, h = bh & 1;
    int p = pt * 8 + w;
    int bg = b * NG_ + h;   // head == group (NH == NG, adjacent reshape)

    float qv = g_qt[((size_t)(b * N1_ + p)) * HID_ + h * C2_ + lane] * SCALE_;

    float iy = 0.f, ix = 0.f;
    if (lane < 9) {
        float2 cc = g_crd[((size_t)bg * NSL_ + lane) * N1_ + p];
        iy = cc.x; ix = cc.y;
    }

    const float* kb = g_kt + (size_t)b * HW_ * HID_ + h * C2_ + lane;
    const float* rb = rpb + (h * NSL_) * C2_ + lane;

    float lg[9];
#pragma unroll
    for (int j = 0; j < 9; j++) {
        float yy = __shfl_sync(0xffffffffu, iy, j);
        float xx = __shfl_sync(0xffffffffu, ix, j);
        float y0f = floorf(yy), x0f = floorf(xx);
        int y0 = (int)y0f, x0 = (int)x0f;
        float wy = yy - y0f, wx = xx - x0f;
        bool yi0 = (y0 >= 0) & (y0 < H_), yi1 = (y0 + 1 >= 0) & (y0 + 1 < H_);
        bool xi0 = (x0 >= 0) & (x0 < W_), xi1 = (x0 + 1 >= 0) & (x0 + 1 < W_);
        int yc0 = min(max(y0, 0), H_ - 1), yc1 = min(max(y0 + 1, 0), H_ - 1);
        int xc0 = min(max(x0, 0), W_ - 1), xc1 = min(max(x0 + 1, 0), W_ - 1);
        float w00 = (yi0 & xi0) ? (1.f - wy) * (1.f - wx) : 0.f;
        float w01 = (yi0 & xi1) ? (1.f - wy) * wx         : 0.f;
        float w10 = (yi1 & xi0) ? wy * (1.f - wx)         : 0.f;
        float w11 = (yi1 & xi1) ? wy * wx                 : 0.f;
        float kv = w00 * kb[(size_t)(yc0 * W_ + xc0) * HID_]
                 + w01 * kb[(size_t)(yc0 * W_ + xc1) * HID_]
                 + w10 * kb[(size_t)(yc1 * W_ + xc0) * HID_]
                 + w11 * kb[(size_t)(yc1 * W_ + xc1) * HID_];
        kv += rb[j * C2_];
        float pr = qv * kv;
#pragma unroll
        for (int o = 16; o; o >>= 1) pr += __shfl_xor_sync(0xffffffffu, pr, o);
        lg[j] = pr;
    }
    // softmax over 9 (redundant per-lane, cheap)
    float m = lg[0];
#pragma unroll
    for (int j = 1; j < 9; j++) m = fmaxf(m, lg[j]);
    float ssum = 0.f;
#pragma unroll
    for (int j = 0; j < 9; j++) { lg[j] = expf(lg[j] - m); ssum += lg[j]; }
    float invs = 1.0f / ssum;

    const float* vb = g_xt + (size_t)b * HW_ * C_ + h * 128 + lane;
    float a0 = 0.f, a1 = 0.f, a2 = 0.f, a3 = 0.f;
#pragma unroll
    for (int j = 0; j < 9; j++) {
        float yy = __shfl_sync(0xffffffffu, iy, j);
        float xx = __shfl_sync(0xffffffffu, ix, j);
        float y0f = floorf(yy), x0f = floorf(xx);
        int y0 = (int)y0f, x0 = (int)x0f;
        float wy = yy - y0f, wx = xx - x0f;
        bool yi0 = (y0 >= 0) & (y0 < H_), yi1 = (y0 + 1 >= 0) & (y0 + 1 < H_);
        bool xi0 = (x0 >= 0) & (x0 < W_), xi1 = (x0 + 1 >= 0) & (x0 + 1 < W_);
        int yc0 = min(max(y0, 0), H_ - 1), yc1 = min(max(y0 + 1, 0), H_ - 1);
        int xc0 = min(max(x0, 0), W_ - 1), xc1 = min(max(x0 + 1, 0), W_ - 1);
        float wj = lg[j] * invs;
        float w00 = (yi0 & xi0) ? (1.f - wy) * (1.f - wx) * wj : 0.f;
        float w01 = (yi0 & xi1) ? (1.f - wy) * wx * wj         : 0.f;
        float w10 = (yi1 & xi0) ? wy * (1.f - wx) * wj         : 0.f;
        float w11 = (yi1 & xi1) ? wy * wx * wj                 : 0.f;
        size_t o00 = (size_t)(yc0 * W_ + xc0) * C_;
        size_t o01 = (size_t)(yc0 * W_ + xc1) * C_;
        size_t o10 = (size_t)(yc1 * W_ + xc0) * C_;
        size_t o11 = (size_t)(yc1 * W_ + xc1) * C_;
        a0 += w00 * vb[o00      ] + w01 * vb[o01      ] + w10 * vb[o10      ] + w11 * vb[o11      ];
        a1 += w00 * vb[o00 + 32 ] + w01 * vb[o01 + 32 ] + w10 * vb[o10 + 32 ] + w11 * vb[o11 + 32 ];
        a2 += w00 * vb[o00 + 64 ] + w01 * vb[o01 + 64 ] + w10 * vb[o10 + 64 ] + w11 * vb[o11 + 64 ];
        a3 += w00 * vb[o00 + 96 ] + w01 * vb[o01 + 96 ] + w10 * vb[o10 + 96 ] + w11 * vb[o11 + 96 ];
    }
    so[lane      ][w] = a0;
    so[lane + 32 ][w] = a1;
    so[lane + 64 ][w] = a2;
    so[lane + 96 ][w] = a3;
    __syncthreads();
    // coalesced output: 128 channels x 8 positions, float4 per thread
    int ch = t >> 1;
    int pp = (t & 1) * 4;
    float4 o4 = make_float4(so[ch][pp], so[ch][pp + 1], so[ch][pp + 2], so[ch][pp + 3]);
    *(float4*)(out + ((size_t)(b * C_ + h * 128 + ch)) * N1_ + pt * 8 + pp) = o4;
}

// ---------------------------------------------------------------------------
extern "C" void kernel_launch(void* const* d_in, const int* in_sizes, int n_in,
                              void* d_out, int out_size) {
    const float* x     = (const float*)d_in[0];
    const float* ln_g  = (const float*)d_in[1];
    const float* ln_b  = (const float*)d_in[2];
    const float* Wq    = (const float*)d_in[3];
    const float* Wk    = (const float*)d_in[4];
    const float* dw_w  = (const float*)d_in[5];
    const float* olg   = (const float*)d_in[6];
    const float* olb   = (const float*)d_in[7];
    const float* off_w = (const float*)d_in[8];
    const float* off_b = (const float*)d_in[9];
    const float* rpb   = (const float*)d_in[10];
    float* out = (float*)d_out;

    (void)in_sizes; (void)n_in; (void)out_size;

    k_transpose<<<dim3(HW_ / 32, C_ / 32, B_), dim3(32, 8)>>>(x);
    k_ln_qk<<<B_ * HW_, 256>>>(ln_g, ln_b, Wq, Wk);
    k_resize<<<(B_ * N1_ * HID_) / 256, 256>>>();
    k_off1<<<(B_ * NG_ * N1_) / 8, 256>>>(dw_w, olg, olb);
    k_off2<<<(B_ * NG_ * N1_) / 8, 256>>>(off_w, off_b);
    k_attn<<<(B_ * NH_ * N1_) / 8, 256>>>(rpb, out);
}

// round 4
// speedup vs baseline: 7.5234x; 7.5234x over previous
#include <cuda_runtime.h>
#include <math.h>

// Problem constants
#define B_ 2
#define C_ 256
#define H_ 48
#define W_ 48
#define HW_ 2304          // 48*48
#define HID_ 64           // hidden = C/RATIO
#define NH_ 2
#define NG_ 2
#define C2_ 32            // hidden/NH
#define GC_ 32            // hidden/NG
#define OH_ 96
#define OW_ 96
#define N1_ 9216          // 96*96
#define KS_ 3
#define NSL_ 9            // KS*KS
#define RF_ 11.0f
#define SCALE_ 0.17677669529663689f   // 32^-0.5
#define RESC_ (47.0f/95.0f)           // (H-1)/(oH-1), align_corners

// Scratch (static device allocations; allowed)
__device__ float  g_xt   [B_ * HW_ * C_];      // x transposed NHWC  (also "v")
__device__ float  g_q48  [B_ * HW_ * HID_];    // q at 48x48, position-major
__device__ float  g_kt   [B_ * HW_ * HID_];    // k, position-major
__device__ float  g_qt   [B_ * N1_ * HID_];    // q upsampled to 96x96, position-major
__device__ float  g_tbuf [B_*NG_ * N1_ * GC_]; // offset-net hidden, position-major
__device__ float2 g_crd  [B_*NG_ * NSL_ * N1_];// sample coords (iy, ix)
__device__ float  g_owt  [9 * 18 * 32];        // off_w transposed: [(tap*18+o)*32+ic]

// ---------------------------------------------------------------------------
// K0: transpose x [B,C,HW] -> x_t [B,HW,C]   (tiled 32x32)
__global__ void k_transpose(const float* __restrict__ x) {
    __shared__ float tile[32][33];
    int b  = blockIdx.z;
    int p0 = blockIdx.x * 32;   // HW tile
    int c0 = blockIdx.y * 32;   // C tile
    int tx = threadIdx.x, ty = threadIdx.y;   // block 32x8
    const float* xb = x + (size_t)b * C_ * HW_;
    float* xtb = g_xt + (size_t)b * HW_ * C_;
#pragma unroll
    for (int k = 0; k < 4; k++) {
        int cc = ty + k * 8;
        tile[cc][tx] = xb[(size_t)(c0 + cc) * HW_ + (p0 + tx)];
    }
    __syncthreads();
#pragma unroll
    for (int k = 0; k < 4; k++) {
        int pp = ty + k * 8;
        xtb[(size_t)(p0 + pp) * C_ + (c0 + tx)] = tile[tx][pp];
    }
}

// Kw: transpose off_w [18][32][9] -> g_owt [(tap*18+o)*32 + ic]
__global__ void k_wprep(const float* __restrict__ off_w) {
    int idx = blockIdx.x * 256 + threadIdx.x;
    if (idx < 18 * 32 * 9) {
        int ic = idx & 31;
        int r  = idx >> 5;       // tap*18 + o
        int o  = r % 18;
        int tap = r / 18;
        g_owt[idx] = off_w[o * (32 * 9) + ic * 9 + tap];
    }
}

// ---------------------------------------------------------------------------
// K1: channel LayerNorm over C=256 + q/k 1x1 convs. One block per (b,p48).
//     Warp-cooperative output dots: lane indexes channel (coalesced W reads).
__global__ void k_ln_qk(const float* __restrict__ ln_g, const float* __restrict__ ln_b,
                        const float* __restrict__ Wq,   const float* __restrict__ Wk) {
    __shared__ float xs[256];
    __shared__ float red[8];
    int t = threadIdx.x;
    int lane = t & 31, w = t >> 5;
    size_t pos = blockIdx.x;             // b*HW + p
    float v = g_xt[pos * C_ + t];
    // mean
    float s = v;
#pragma unroll
    for (int o = 16; o; o >>= 1) s += __shfl_xor_sync(0xffffffffu, s, o);
    if (lane == 0) red[w] = s;
    __syncthreads();
    float tot = 0.f;
#pragma unroll
    for (int i = 0; i < 8; i++) tot += red[i];
    float mean = tot * (1.0f / 256.0f);
    __syncthreads();
    // var
    float d = v - mean;
    float vv = d * d;
#pragma unroll
    for (int o = 16; o; o >>= 1) vv += __shfl_xor_sync(0xffffffffu, vv, o);
    if (lane == 0) red[w] = vv;
    __syncthreads();
    tot = 0.f;
#pragma unroll
    for (int i = 0; i < 8; i++) tot += red[i];
    float inv = rsqrtf(tot * (1.0f / 256.0f) + 1e-5f);
    xs[t] = d * inv * ln_g[t] + ln_b[t];
    __syncthreads();
    // 128 outputs (64 q + 64 k): warp w does outputs w*16 .. w*16+15.
    // Lane = channel chunk -> coalesced weight loads, shfl reduce.
#pragma unroll
    for (int oi = 0; oi < 16; oi++) {
        int o = w * 16 + oi;
        const float* Wrow = (o < 64) ? (Wq + (size_t)o * 256) : (Wk + (size_t)(o - 64) * 256);
        float acc = 0.f;
#pragma unroll
        for (int i = 0; i < 8; i++) acc += Wrow[i * 32 + lane] * xs[i * 32 + lane];
#pragma unroll
        for (int sh = 16; sh; sh >>= 1) acc += __shfl_xor_sync(0xffffffffu, acc, sh);
        if (lane == 0) {
            if (o < 64) g_q48[pos * HID_ + o]        = acc;
            else        g_kt [pos * HID_ + (o - 64)] = acc;
        }
    }
}

// ---------------------------------------------------------------------------
// K2: bilinear upsample q48 -> qt (align_corners), elementwise gather
__global__ void k_resize() {
    int idx = blockIdx.x * 256 + threadIdx.x;      // B*N1*HID = 1,179,648 exactly
    int c = idx & 63;
    int p = (idx >> 6) % N1_;
    int b = (idx >> 6) / N1_;
    int oy = p / OW_, ox = p % OW_;
    float ys = oy * RESC_;
    float xsf = ox * RESC_;
    int y0 = min(max((int)floorf(ys), 0), H_ - 2);
    int x0 = min(max((int)floorf(xsf), 0), W_ - 2);
    float wy = ys - (float)y0, wx = xsf - (float)x0;
    const float* base = g_q48 + (size_t)b * HW_ * HID_;
    float v00 = base[((y0    ) * W_ + x0    ) * HID_ + c];
    float v01 = base[((y0    ) * W_ + x0 + 1) * HID_ + c];
    float v10 = base[((y0 + 1) * W_ + x0    ) * HID_ + c];
    float v11 = base[((y0 + 1) * W_ + x0 + 1) * HID_ + c];
    g_qt[idx] = (1.f - wy) * ((1.f - wx) * v00 + wx * v01)
              +         wy * ((1.f - wx) * v10 + wx * v11);
}

// ---------------------------------------------------------------------------
// K3: offset net stage 1: depthwise 3x3 conv + channel LN(32) + exact GELU.
//     8 warps/block, one warp per (bg,p96).
__global__ void k_off1(const float* __restrict__ dw_w,
                       const float* __restrict__ og, const float* __restrict__ ob) {
    int t = threadIdx.x;
    int ch = t & 31, u = t >> 5;
    int gid = blockIdx.x * 8 + u;        // < 4*9216
    int bg = gid / N1_, p = gid % N1_;
    int b = bg >> 1, g = bg & 1;
    int y = p / OW_, x = p % OW_;
    const float* qb = g_qt + (size_t)b * N1_ * HID_ + g * GC_ + ch;
    float acc = 0.0f;
#pragma unroll
    for (int ky = 0; ky < 3; ky++) {
        int ny = y + ky - 1;
        if (ny < 0 || ny >= OH_) continue;
#pragma unroll
        for (int kx = 0; kx < 3; kx++) {
            int nx = x + kx - 1;
            if (nx < 0 || nx >= OW_) continue;
            acc += qb[(size_t)(ny * OW_ + nx) * HID_] * dw_w[ch * 9 + ky * 3 + kx];
        }
    }
    // warp LN over 32 channels
    float s = acc;
#pragma unroll
    for (int o = 16; o; o >>= 1) s += __shfl_xor_sync(0xffffffffu, s, o);
    float mean = s * (1.0f / 32.0f);
    float d = acc - mean;
    float vv = d * d;
#pragma unroll
    for (int o = 16; o; o >>= 1) vv += __shfl_xor_sync(0xffffffffu, vv, o);
    float inv = rsqrtf(vv * (1.0f / 32.0f) + 1e-5f);
    float tn = d * inv * og[ch] + ob[ch];
    float ge = 0.5f * tn * (1.0f + erff(tn * 0.70710678118654752f));
    g_tbuf[(size_t)gid * GC_ + ch] = ge;
}

// ---------------------------------------------------------------------------
// K4: offset net stage 2: 3x3 conv 32->18 + bias + tanh -> sample coords.
//     Lane = INPUT channel (parallel over ic); weights pre-transposed so
//     weight loads are lane-consecutive (coalesced, L1-hot). 18 warp-reduces.
__global__ void k_off2(const float* __restrict__ off_b) {
    __shared__ float pr[8][20];
    int t = threadIdx.x;
    int lane = t & 31, u = t >> 5;
    int gid = blockIdx.x * 8 + u;
    int bg = gid / N1_, p = gid % N1_;
    int y = p / OW_, x = p % OW_;
    const float* tb = g_tbuf + (size_t)bg * N1_ * GC_;
    float in[9];
#pragma unroll
    for (int tap = 0; tap < 9; tap++) {
        int ny = y + tap / 3 - 1, nx = x + tap % 3 - 1;
        bool inb = ((unsigned)ny < OH_) && ((unsigned)nx < OW_);
        in[tap] = inb ? tb[(size_t)(ny * OW_ + nx) * GC_ + lane] : 0.0f;
    }
#pragma unroll
    for (int o = 0; o < 18; o++) {
        float acc = 0.f;
#pragma unroll
        for (int tap = 0; tap < 9; tap++)
            acc += in[tap] * g_owt[(tap * 18 + o) * 32 + lane];
#pragma unroll
        for (int sh = 16; sh; sh >>= 1) acc += __shfl_xor_sync(0xffffffffu, acc, sh);
        if (lane == 0) pr[u][o] = acc + off_b[o];
    }
    __syncwarp();
    if (lane < 9) {
        int ky = lane / 3, kx = lane % 3;
        float py = tanhf(pr[u][2 * lane    ]) * RF_ + (float)(ky - 1) + (float)y;
        float px = tanhf(pr[u][2 * lane + 1]) * RF_ + (float)(kx - 1) + (float)x;
        g_crd[((size_t)bg * NSL_ + lane) * N1_ + p] = make_float2(py * RESC_, px * RESC_);
    }
}

// ---------------------------------------------------------------------------
// K5: fused grid-sample + attention + output. One warp per (b,h,p96).
//     8 warps/block handle 8 consecutive p for one (b,h); smem-staged output.
__global__ void k_attn(const float* __restrict__ rpb, float* __restrict__ out) {
    __shared__ float so[128][9];   // [channel][warp], padded: conflict-free
    int t = threadIdx.x;
    int lane = t & 31, w = t >> 5;
    int bh = blockIdx.x / (N1_ / 8);
    int pt = blockIdx.x % (N1_ / 8);
    int b = bh >> 1, h = bh & 1;
    int p = pt * 8 + w;
    int bg = b * NG_ + h;   // head == group (NH == NG, adjacent reshape)

    float qv = g_qt[((size_t)(b * N1_ + p)) * HID_ + h * C2_ + lane] * SCALE_;

    float iy = 0.f, ix = 0.f;
    if (lane < 9) {
        float2 cc = g_crd[((size_t)bg * NSL_ + lane) * N1_ + p];
        iy = cc.x; ix = cc.y;
    }

    const float* kb = g_kt + (size_t)b * HW_ * HID_ + h * C2_ + lane;
    const float* rb = rpb + (h * NSL_) * C2_ + lane;

    float lg[9];
#pragma unroll
    for (int j = 0; j < 9; j++) {
        float yy = __shfl_sync(0xffffffffu, iy, j);
        float xx = __shfl_sync(0xffffffffu, ix, j);
        float y0f = floorf(yy), x0f = floorf(xx);
        int y0 = (int)y0f, x0 = (int)x0f;
        float wy = yy - y0f, wx = xx - x0f;
        bool yi0 = (y0 >= 0) & (y0 < H_), yi1 = (y0 + 1 >= 0) & (y0 + 1 < H_);
        bool xi0 = (x0 >= 0) & (x0 < W_), xi1 = (x0 + 1 >= 0) & (x0 + 1 < W_);
        int yc0 = min(max(y0, 0), H_ - 1), yc1 = min(max(y0 + 1, 0), H_ - 1);
        int xc0 = min(max(x0, 0), W_ - 1), xc1 = min(max(x0 + 1, 0), W_ - 1);
        float w00 = (yi0 & xi0) ? (1.f - wy) * (1.f - wx) : 0.f;
        float w01 = (yi0 & xi1) ? (1.f - wy) * wx         : 0.f;
        float w10 = (yi1 & xi0) ? wy * (1.f - wx)         : 0.f;
        float w11 = (yi1 & xi1) ? wy * wx                 : 0.f;
        float kv = w00 * kb[(size_t)(yc0 * W_ + xc0) * HID_]
                 + w01 * kb[(size_t)(yc0 * W_ + xc1) * HID_]
                 + w10 * kb[(size_t)(yc1 * W_ + xc0) * HID_]
                 + w11 * kb[(size_t)(yc1 * W_ + xc1) * HID_];
        kv += rb[j * C2_];
        float pr = qv * kv;
#pragma unroll
        for (int o = 16; o; o >>= 1) pr += __shfl_xor_sync(0xffffffffu, pr, o);
        lg[j] = pr;
    }
    // softmax over 9 (redundant per-lane, cheap)
    float m = lg[0];
#pragma unroll
    for (int j = 1; j < 9; j++) m = fmaxf(m, lg[j]);
    float ssum = 0.f;
#pragma unroll
    for (int j = 0; j < 9; j++) { lg[j] = expf(lg[j] - m); ssum += lg[j]; }
    float invs = 1.0f / ssum;

    const float* vb = g_xt + (size_t)b * HW_ * C_ + h * 128 + lane;
    float a0 = 0.f, a1 = 0.f, a2 = 0.f, a3 = 0.f;
#pragma unroll
    for (int j = 0; j < 9; j++) {
        float yy = __shfl_sync(0xffffffffu, iy, j);
        float xx = __shfl_sync(0xffffffffu, ix, j);
        float y0f = floorf(yy), x0f = floorf(xx);
        int y0 = (int)y0f, x0 = (int)x0f;
        float wy = yy - y0f, wx = xx - x0f;
        bool yi0 = (y0 >= 0) & (y0 < H_), yi1 = (y0 + 1 >= 0) & (y0 + 1 < H_);
        bool xi0 = (x0 >= 0) & (x0 < W_), xi1 = (x0 + 1 >= 0) & (x0 + 1 < W_);
        int yc0 = min(max(y0, 0), H_ - 1), yc1 = min(max(y0 + 1, 0), H_ - 1);
        int xc0 = min(max(x0, 0), W_ - 1), xc1 = min(max(x0 + 1, 0), W_ - 1);
        float wj = lg[j] * invs;
        float w00 = (yi0 & xi0) ? (1.f - wy) * (1.f - wx) * wj : 0.f;
        float w01 = (yi0 & xi1) ? (1.f - wy) * wx * wj         : 0.f;
        float w10 = (yi1 & xi0) ? wy * (1.f - wx) * wj         : 0.f;
        float w11 = (yi1 & xi1) ? wy * wx * wj                 : 0.f;
        size_t o00 = (size_t)(yc0 * W_ + xc0) * C_;
        size_t o01 = (size_t)(yc0 * W_ + xc1) * C_;
        size_t o10 = (size_t)(yc1 * W_ + xc0) * C_;
        size_t o11 = (size_t)(yc1 * W_ + xc1) * C_;
        a0 += w00 * vb[o00      ] + w01 * vb[o01      ] + w10 * vb[o10      ] + w11 * vb[o11      ];
        a1 += w00 * vb[o00 + 32 ] + w01 * vb[o01 + 32 ] + w10 * vb[o10 + 32 ] + w11 * vb[o11 + 32 ];
        a2 += w00 * vb[o00 + 64 ] + w01 * vb[o01 + 64 ] + w10 * vb[o10 + 64 ] + w11 * vb[o11 + 64 ];
        a3 += w00 * vb[o00 + 96 ] + w01 * vb[o01 + 96 ] + w10 * vb[o10 + 96 ] + w11 * vb[o11 + 96 ];
    }
    so[lane      ][w] = a0;
    so[lane + 32 ][w] = a1;
    so[lane + 64 ][w] = a2;
    so[lane + 96 ][w] = a3;
    __syncthreads();
    // coalesced output: 128 channels x 8 positions, float4 per thread
    int ch = t >> 1;
    int pp = (t & 1) * 4;
    float4 o4 = make_float4(so[ch][pp], so[ch][pp + 1], so[ch][pp + 2], so[ch][pp + 3]);
    *(float4*)(out + ((size_t)(b * C_ + h * 128 + ch)) * N1_ + pt * 8 + pp) = o4;
}

// ---------------------------------------------------------------------------
extern "C" void kernel_launch(void* const* d_in, const int* in_sizes, int n_in,
                              void* d_out, int out_size) {
    const float* x     = (const float*)d_in[0];
    const float* ln_g  = (const float*)d_in[1];
    const float* ln_b  = (const float*)d_in[2];
    const float* Wq    = (const float*)d_in[3];
    const float* Wk    = (const float*)d_in[4];
    const float* dw_w  = (const float*)d_in[5];
    const float* olg   = (const float*)d_in[6];
    const float* olb   = (const float*)d_in[7];
    const float* off_w = (const float*)d_in[8];
    const float* off_b = (const float*)d_in[9];
    const float* rpb   = (const float*)d_in[10];
    float* out = (float*)d_out;

    (void)in_sizes; (void)n_in; (void)out_size;

    k_transpose<<<dim3(HW_ / 32, C_ / 32, B_), dim3(32, 8)>>>(x);
    k_wprep<<<(18 * 32 * 9 + 255) / 256, 256>>>(off_w);
    k_ln_qk<<<B_ * HW_, 256>>>(ln_g, ln_b, Wq, Wk);
    k_resize<<<(B_ * N1_ * HID_) / 256, 256>>>();
    k_off1<<<(B_ * NG_ * N1_) / 8, 256>>>(dw_w, olg, olb);
    k_off2<<<(B_ * NG_ * N1_) / 8, 256>>>(olb ? off_b : off_b);
    k_attn<<<(B_ * NH_ * N1_) / 8, 256>>>(rpb, out);
}

// round 5
// speedup vs baseline: 8.5498x; 1.1364x over previous
#include <cuda_runtime.h>
#include <math.h>

// Problem constants
#define B_ 2
#define C_ 256
#define H_ 48
#define W_ 48
#define HW_ 2304          // 48*48
#define HID_ 64           // hidden = C/RATIO
#define NH_ 2
#define NG_ 2
#define C2_ 32            // hidden/NH
#define GC_ 32            // hidden/NG
#define OH_ 96
#define OW_ 96
#define N1_ 9216          // 96*96
#define KS_ 3
#define NSL_ 9            // KS*KS
#define RF_ 11.0f
#define SCALE_ 0.17677669529663689f   // 32^-0.5
#define RESC_ (47.0f/95.0f)           // (H-1)/(oH-1), align_corners

// Scratch (static device allocations; allowed)
__device__ float  g_xt   [B_ * HW_ * C_];      // x transposed NHWC  (also "v")
__device__ float  g_q48  [B_ * HW_ * HID_];    // q at 48x48, position-major
__device__ float  g_kt   [B_ * HW_ * HID_];    // k, position-major
__device__ float  g_qt   [B_ * N1_ * HID_];    // q upsampled to 96x96, position-major
__device__ float  g_tbuf [B_*NG_ * N1_ * GC_]; // offset-net hidden, position-major
__device__ float2 g_crd  [B_*NG_ * NSL_ * N1_];// sample coords (iy, ix)
__device__ float  g_owt  [9 * 18 * 32];        // off_w transposed: [(tap*18+o)*32+ic]

// ---------------------------------------------------------------------------
// K0: transpose x [B,C,HW] -> x_t [B,HW,C]   (tiled 32x32)
__global__ void k_transpose(const float* __restrict__ x) {
    __shared__ float tile[32][33];
    int b  = blockIdx.z;
    int p0 = blockIdx.x * 32;   // HW tile
    int c0 = blockIdx.y * 32;   // C tile
    int tx = threadIdx.x, ty = threadIdx.y;   // block 32x8
    const float* xb = x + (size_t)b * C_ * HW_;
    float* xtb = g_xt + (size_t)b * HW_ * C_;
#pragma unroll
    for (int k = 0; k < 4; k++) {
        int cc = ty + k * 8;
        tile[cc][tx] = xb[(size_t)(c0 + cc) * HW_ + (p0 + tx)];
    }
    __syncthreads();
#pragma unroll
    for (int k = 0; k < 4; k++) {
        int pp = ty + k * 8;
        xtb[(size_t)(p0 + pp) * C_ + (c0 + tx)] = tile[tx][pp];
    }
}

// Kw: transpose off_w [18][32][9] -> g_owt [(tap*18+o)*32 + ic]
__global__ void k_wprep(const float* __restrict__ off_w) {
    int idx = blockIdx.x * 256 + threadIdx.x;
    if (idx < 18 * 32 * 9) {
        int ic = idx & 31;
        int r  = idx >> 5;       // tap*18 + o
        int o  = r % 18;
        int tap = r / 18;
        g_owt[idx] = off_w[o * (32 * 9) + ic * 9 + tap];
    }
}

// ---------------------------------------------------------------------------
// K1: channel LayerNorm over C=256 + q/k 1x1 convs. One block per (b,p48).
//     Warp-cooperative output dots: lane indexes channel (coalesced W reads).
__global__ void k_ln_qk(const float* __restrict__ ln_g, const float* __restrict__ ln_b,
                        const float* __restrict__ Wq,   const float* __restrict__ Wk) {
    __shared__ float xs[256];
    __shared__ float red[8];
    int t = threadIdx.x;
    int lane = t & 31, w = t >> 5;
    size_t pos = blockIdx.x;             // b*HW + p
    float v = g_xt[pos * C_ + t];
    // mean
    float s = v;
#pragma unroll
    for (int o = 16; o; o >>= 1) s += __shfl_xor_sync(0xffffffffu, s, o);
    if (lane == 0) red[w] = s;
    __syncthreads();
    float tot = 0.f;
#pragma unroll
    for (int i = 0; i < 8; i++) tot += red[i];
    float mean = tot * (1.0f / 256.0f);
    __syncthreads();
    // var
    float d = v - mean;
    float vv = d * d;
#pragma unroll
    for (int o = 16; o; o >>= 1) vv += __shfl_xor_sync(0xffffffffu, vv, o);
    if (lane == 0) red[w] = vv;
    __syncthreads();
    tot = 0.f;
#pragma unroll
    for (int i = 0; i < 8; i++) tot += red[i];
    float inv = rsqrtf(tot * (1.0f / 256.0f) + 1e-5f);
    xs[t] = d * inv * ln_g[t] + ln_b[t];
    __syncthreads();
    // 128 outputs (64 q + 64 k): warp w does outputs w*16 .. w*16+15.
    // Lane = 4-channel chunk -> float4 coalesced weight loads, shfl reduce.
    const float4* xs4 = (const float4*)xs;
    float4 xa = xs4[lane], xb4 = xs4[lane + 32];
#pragma unroll
    for (int oi = 0; oi < 16; oi++) {
        int o = w * 16 + oi;
        const float4* Wrow = (const float4*)((o < 64) ? (Wq + (size_t)o * 256)
                                                      : (Wk + (size_t)(o - 64) * 256));
        float4 wa = Wrow[lane], wb = Wrow[lane + 32];
        float acc = wa.x * xa.x + wa.y * xa.y + wa.z * xa.z + wa.w * xa.w
                  + wb.x * xb4.x + wb.y * xb4.y + wb.z * xb4.z + wb.w * xb4.w;
#pragma unroll
        for (int sh = 16; sh; sh >>= 1) acc += __shfl_xor_sync(0xffffffffu, acc, sh);
        if (lane == 0) {
            if (o < 64) g_q48[pos * HID_ + o]        = acc;
            else        g_kt [pos * HID_ + (o - 64)] = acc;
        }
    }
}

// ---------------------------------------------------------------------------
// K2: bilinear upsample q48 -> qt (align_corners), float4-vectorized gather
__global__ void k_resize() {
    int idx = blockIdx.x * 256 + threadIdx.x;      // B*N1*16 float4s = 294,912
    int c4 = idx & 15;
    int p = (idx >> 4) % N1_;
    int b = (idx >> 4) / N1_;
    int oy = p / OW_, ox = p % OW_;
    float ys = oy * RESC_;
    float xsf = ox * RESC_;
    int y0 = min(max((int)floorf(ys), 0), H_ - 2);
    int x0 = min(max((int)floorf(xsf), 0), W_ - 2);
    float wy = ys - (float)y0, wx = xsf - (float)x0;
    const float4* base = (const float4*)(g_q48 + (size_t)b * HW_ * HID_);
    float4 v00 = base[((y0    ) * W_ + x0    ) * 16 + c4];
    float4 v01 = base[((y0    ) * W_ + x0 + 1) * 16 + c4];
    float4 v10 = base[((y0 + 1) * W_ + x0    ) * 16 + c4];
    float4 v11 = base[((y0 + 1) * W_ + x0 + 1) * 16 + c4];
    float a = (1.f - wy) * (1.f - wx), bq = (1.f - wy) * wx;
    float c = wy * (1.f - wx), dq = wy * wx;
    float4 r;
    r.x = a * v00.x + bq * v01.x + c * v10.x + dq * v11.x;
    r.y = a * v00.y + bq * v01.y + c * v10.y + dq * v11.y;
    r.z = a * v00.z + bq * v01.z + c * v10.z + dq * v11.z;
    r.w = a * v00.w + bq * v01.w + c * v10.w + dq * v11.w;
    ((float4*)g_qt)[idx] = r;
}

// ---------------------------------------------------------------------------
// K3: offset net stage 1: depthwise 3x3 conv + channel LN(32) + exact GELU.
//     8 warps/block, one warp per (bg,p96).
__global__ void k_off1(const float* __restrict__ dw_w,
                       const float* __restrict__ og, const float* __restrict__ ob) {
    int t = threadIdx.x;
    int ch = t & 31, u = t >> 5;
    int gid = blockIdx.x * 8 + u;        // < 4*9216
    int bg = gid / N1_, p = gid % N1_;
    int b = bg >> 1, g = bg & 1;
    int y = p / OW_, x = p % OW_;
    const float* qb = g_qt + (size_t)b * N1_ * HID_ + g * GC_ + ch;
    float acc = 0.0f;
#pragma unroll
    for (int ky = 0; ky < 3; ky++) {
        int ny = y + ky - 1;
        if (ny < 0 || ny >= OH_) continue;
#pragma unroll
        for (int kx = 0; kx < 3; kx++) {
            int nx = x + kx - 1;
            if (nx < 0 || nx >= OW_) continue;
            acc += qb[(size_t)(ny * OW_ + nx) * HID_] * dw_w[ch * 9 + ky * 3 + kx];
        }
    }
    // warp LN over 32 channels
    float s = acc;
#pragma unroll
    for (int o = 16; o; o >>= 1) s += __shfl_xor_sync(0xffffffffu, s, o);
    float mean = s * (1.0f / 32.0f);
    float d = acc - mean;
    float vv = d * d;
#pragma unroll
    for (int o = 16; o; o >>= 1) vv += __shfl_xor_sync(0xffffffffu, vv, o);
    float inv = rsqrtf(vv * (1.0f / 32.0f) + 1e-5f);
    float tn = d * inv * og[ch] + ob[ch];
    float ge = 0.5f * tn * (1.0f + erff(tn * 0.70710678118654752f));
    g_tbuf[(size_t)gid * GC_ + ch] = ge;
}

// ---------------------------------------------------------------------------
// K4: offset net stage 2: 3x3 conv 32->18 + bias + tanh -> sample coords.
//     Lane = INPUT channel; weights pre-transposed -> coalesced L1-hot loads.
__global__ void k_off2(const float* __restrict__ off_b) {
    __shared__ float pr[8][20];
    int t = threadIdx.x;
    int lane = t & 31, u = t >> 5;
    int gid = blockIdx.x * 8 + u;
    int bg = gid / N1_, p = gid % N1_;
    int y = p / OW_, x = p % OW_;
    const float* tb = g_tbuf + (size_t)bg * N1_ * GC_;
    float in[9];
#pragma unroll
    for (int tap = 0; tap < 9; tap++) {
        int ny = y + tap / 3 - 1, nx = x + tap % 3 - 1;
        bool inb = ((unsigned)ny < OH_) && ((unsigned)nx < OW_);
        in[tap] = inb ? tb[(size_t)(ny * OW_ + nx) * GC_ + lane] : 0.0f;
    }
#pragma unroll
    for (int o = 0; o < 18; o++) {
        float acc = 0.f;
#pragma unroll
        for (int tap = 0; tap < 9; tap++)
            acc += in[tap] * g_owt[(tap * 18 + o) * 32 + lane];
#pragma unroll
        for (int sh = 16; sh; sh >>= 1) acc += __shfl_xor_sync(0xffffffffu, acc, sh);
        if (lane == 0) pr[u][o] = acc + off_b[o];
    }
    __syncwarp();
    if (lane < 9) {
        int ky = lane / 3, kx = lane % 3;
        float py = tanhf(pr[u][2 * lane    ]) * RF_ + (float)(ky - 1) + (float)y;
        float px = tanhf(pr[u][2 * lane + 1]) * RF_ + (float)(kx - 1) + (float)x;
        g_crd[((size_t)bg * NSL_ + lane) * N1_ + p] = make_float2(py * RESC_, px * RESC_);
    }
}

// ---------------------------------------------------------------------------
// K5: fused grid-sample + attention + output, single pass (online softmax).
//     One warp per (b,h,p96). v gathered as float4 (lane = 4 channels).
__global__ void k_attn(const float* __restrict__ rpb, float* __restrict__ out) {
    __shared__ float4 so4[8][32];   // [warp][lane] staging
    int t = threadIdx.x;
    int lane = t & 31, w = t >> 5;
    int bh = blockIdx.x / (N1_ / 8);
    int pt = blockIdx.x % (N1_ / 8);
    int b = bh >> 1, h = bh & 1;
    int p = pt * 8 + w;
    int bg = b * NG_ + h;   // head == group (NH == NG, adjacent reshape)

    float qv = g_qt[((size_t)(b * N1_ + p)) * HID_ + h * C2_ + lane] * SCALE_;

    float iy = 0.f, ix = 0.f;
    if (lane < 9) {
        float2 cc = g_crd[((size_t)bg * NSL_ + lane) * N1_ + p];
        iy = cc.x; ix = cc.y;
    }

    const float*  kb = g_kt + (size_t)b * HW_ * HID_ + h * C2_ + lane;
    const float4* vb = (const float4*)(g_xt + (size_t)b * HW_ * C_ + h * 128) + lane;

    float rpbv[9];
#pragma unroll
    for (int j = 0; j < 9; j++) rpbv[j] = rpb[(h * NSL_ + j) * C2_ + lane];

    float m = -1e30f, ssum = 0.f;
    float ax = 0.f, ay = 0.f, az = 0.f, aw = 0.f;

#pragma unroll
    for (int j = 0; j < 9; j++) {
        float yy = __shfl_sync(0xffffffffu, iy, j);
        float xx = __shfl_sync(0xffffffffu, ix, j);
        float y0f = floorf(yy), x0f = floorf(xx);
        int y0 = (int)y0f, x0 = (int)x0f;
        float wy = yy - y0f, wx = xx - x0f;
        bool yi0 = (y0 >= 0) & (y0 < H_), yi1 = (y0 + 1 >= 0) & (y0 + 1 < H_);
        bool xi0 = (x0 >= 0) & (x0 < W_), xi1 = (x0 + 1 >= 0) & (x0 + 1 < W_);
        int yc0 = min(max(y0, 0), H_ - 1), yc1 = min(max(y0 + 1, 0), H_ - 1);
        int xc0 = min(max(x0, 0), W_ - 1), xc1 = min(max(x0 + 1, 0), W_ - 1);
        float w00 = (yi0 & xi0) ? (1.f - wy) * (1.f - wx) : 0.f;
        float w01 = (yi0 & xi1) ? (1.f - wy) * wx         : 0.f;
        float w10 = (yi1 & xi0) ? wy * (1.f - wx)         : 0.f;
        float w11 = (yi1 & xi1) ? wy * wx                 : 0.f;
        int i00 = yc0 * W_ + xc0, i01 = yc0 * W_ + xc1;
        int i10 = yc1 * W_ + xc0, i11 = yc1 * W_ + xc1;
        // logit: k gather + rpb + q dot (warp reduce)
        float kv = w00 * kb[(size_t)i00 * HID_] + w01 * kb[(size_t)i01 * HID_]
                 + w10 * kb[(size_t)i10 * HID_] + w11 * kb[(size_t)i11 * HID_]
                 + rpbv[j];
        float pr = qv * kv;
#pragma unroll
        for (int o = 16; o; o >>= 1) pr += __shfl_xor_sync(0xffffffffu, pr, o);
        // online softmax update
        float mn = fmaxf(m, pr);
        float sc = __expf(m - mn);
        float wj = __expf(pr - mn);
        ssum = ssum * sc + wj;
        m = mn;
        // v gather (float4: 4 consecutive channels per lane)
        float4 v00 = vb[(size_t)i00 * 64], v01 = vb[(size_t)i01 * 64];
        float4 v10 = vb[(size_t)i10 * 64], v11 = vb[(size_t)i11 * 64];
        ax = ax * sc + wj * (w00 * v00.x + w01 * v01.x + w10 * v10.x + w11 * v11.x);
        ay = ay * sc + wj * (w00 * v00.y + w01 * v01.y + w10 * v10.y + w11 * v11.y);
        az = az * sc + wj * (w00 * v00.z + w01 * v01.z + w10 * v10.z + w11 * v11.z);
        aw = aw * sc + wj * (w00 * v00.w + w01 * v01.w + w10 * v10.w + w11 * v11.w);
    }
    float invs = 1.0f / ssum;
    so4[w][lane] = make_float4(ax * invs, ay * invs, az * invs, aw * invs);
    __syncthreads();
    // coalesced output: 128 channels x 8 positions, float4 per thread
    const float* sof = (const float*)so4;   // [warp][128ch]
    int ch = t >> 1;
    int pp = (t & 1) * 4;
    float4 o4 = make_float4(sof[(pp + 0) * 128 + ch], sof[(pp + 1) * 128 + ch],
                            sof[(pp + 2) * 128 + ch], sof[(pp + 3) * 128 + ch]);
    *(float4*)(out + ((size_t)(b * C_ + h * 128 + ch)) * N1_ + pt * 8 + pp) = o4;
}

// ---------------------------------------------------------------------------
extern "C" void kernel_launch(void* const* d_in, const int* in_sizes, int n_in,
                              void* d_out, int out_size) {
    const float* x     = (const float*)d_in[0];
    const float* ln_g  = (const float*)d_in[1];
    const float* ln_b  = (const float*)d_in[2];
    const float* Wq    = (const float*)d_in[3];
    const float* Wk    = (const float*)d_in[4];
    const float* dw_w  = (const float*)d_in[5];
    const float* olg   = (const float*)d_in[6];
    const float* olb   = (const float*)d_in[7];
    const float* off_w = (const float*)d_in[8];
    const float* off_b = (const float*)d_in[9];
    const float* rpb   = (const float*)d_in[10];
    float* out = (float*)d_out;

    (void)in_sizes; (void)n_in; (void)out_size;

    k_transpose<<<dim3(HW_ / 32, C_ / 32, B_), dim3(32, 8)>>>(x);
    k_wprep<<<(18 * 32 * 9 + 255) / 256, 256>>>(off_w);
    k_ln_qk<<<B_ * HW_, 256>>>(ln_g, ln_b, Wq, Wk);
    k_resize<<<(B_ * N1_ * 16) / 256, 256>>>();
    k_off1<<<(B_ * NG_ * N1_) / 8, 256>>>(dw_w, olg, olb);
    k_off2<<<(B_ * NG_ * N1_) / 8, 256>>>(off_b);
    k_attn<<<(B_ * NH_ * N1_) / 8, 256>>>(rpb, out);
}

// round 6
// speedup vs baseline: 9.4570x; 1.1061x over previous
#include <cuda_runtime.h>
#include <math.h>

// Problem constants
#define B_ 2
#define C_ 256
#define H_ 48
#define W_ 48
#define HW_ 2304          // 48*48
#define HID_ 64           // hidden = C/RATIO
#define NH_ 2
#define NG_ 2
#define C2_ 32            // hidden/NH
#define GC_ 32            // hidden/NG
#define OH_ 96
#define OW_ 96
#define N1_ 9216          // 96*96
#define KS_ 3
#define NSL_ 9            // KS*KS
#define RF_ 11.0f
#define SCALE_ 0.17677669529663689f   // 32^-0.5
#define RESC_ (47.0f/95.0f)           // (H-1)/(oH-1), align_corners

// Scratch (static device allocations; allowed)
__device__ float  g_xt   [B_ * HW_ * C_];      // x transposed NHWC  (also "v")
__device__ float  g_q48  [B_ * HW_ * HID_];    // q at 48x48, position-major
__device__ float  g_kt   [B_ * HW_ * HID_];    // k, position-major
__device__ float  g_qt   [B_ * N1_ * HID_];    // q upsampled to 96x96, position-major
__device__ float  g_tbuf [B_*NG_ * N1_ * GC_]; // offset-net hidden, position-major
__device__ float  g_owt  [9 * 18 * 32];        // off_w transposed: [(tap*18+o)*32+ic]
__device__ float  g_wt   [256 * 128];          // qk weights transposed: [c][o] o:0-63=q,64-127=k
__device__ float4 g_tw   [B_*NG_ * NSL_ * N1_];// per-tap bilinear weights (w00,w01,w10,w11)
__device__ int2   g_ti   [B_*NG_ * NSL_ * N1_];// per-tap packed corner indices

// ---------------------------------------------------------------------------
// K0: transpose x [B,C,HW] -> x_t [B,HW,C]   (tiled 32x32)
__global__ void k_transpose(const float* __restrict__ x) {
    __shared__ float tile[32][33];
    int b  = blockIdx.z;
    int p0 = blockIdx.x * 32;   // HW tile
    int c0 = blockIdx.y * 32;   // C tile
    int tx = threadIdx.x, ty = threadIdx.y;   // block 32x8
    const float* xb = x + (size_t)b * C_ * HW_;
    float* xtb = g_xt + (size_t)b * HW_ * C_;
#pragma unroll
    for (int k = 0; k < 4; k++) {
        int cc = ty + k * 8;
        tile[cc][tx] = xb[(size_t)(c0 + cc) * HW_ + (p0 + tx)];
    }
    __syncthreads();
#pragma unroll
    for (int k = 0; k < 4; k++) {
        int pp = ty + k * 8;
        xtb[(size_t)(p0 + pp) * C_ + (c0 + tx)] = tile[tx][pp];
    }
}

// Kw: weight prep. idx<32768: g_wt[c*128+o] from Wq/Wk. Then off_w transpose.
__global__ void k_wprep(const float* __restrict__ Wq, const float* __restrict__ Wk,
                        const float* __restrict__ off_w) {
    int idx = blockIdx.x * 256 + threadIdx.x;
    if (idx < 256 * 128) {
        int c = idx >> 7, o = idx & 127;
        g_wt[idx] = (o < 64) ? Wq[o * 256 + c] : Wk[(o - 64) * 256 + c];
    } else if (idx < 256 * 128 + 18 * 32 * 9) {
        int j = idx - 256 * 128;
        int ic = j & 31;
        int r  = j >> 5;       // tap*18 + o
        int o  = r % 18;
        int tap = r / 18;
        g_owt[j] = off_w[o * (32 * 9) + ic * 9 + tap];
    }
}

// ---------------------------------------------------------------------------
// K1: channel LN(256) + q/k 1x1 conv. Warp = 4 positions; block = 32 positions.
//     GEMM uses transposed weights (lane = 4 consecutive outputs), each W
//     float4 loaded once and applied to 4 positions (4x W-traffic reuse).
__global__ void k_ln_qk(const float* __restrict__ ln_g, const float* __restrict__ ln_b) {
    __shared__ float smx[32][256];
    int t = threadIdx.x;
    int lane = t & 31, w = t >> 5;
    int pbase = blockIdx.x * 32 + w * 4;       // global position of this warp's first

    const float4* g4 = (const float4*)ln_g;
    const float4* b4 = (const float4*)ln_b;
    float4 ga = g4[lane], gb = g4[lane + 32];
    float4 ba = b4[lane], bb = b4[lane + 32];

    // LN for 4 positions
#pragma unroll
    for (int i = 0; i < 4; i++) {
        size_t pos = pbase + i;
        const float4* xt4 = (const float4*)(g_xt + pos * C_);
        float4 va = xt4[lane], vb = xt4[lane + 32];
        float s = va.x + va.y + va.z + va.w + vb.x + vb.y + vb.z + vb.w;
#pragma unroll
        for (int o = 16; o; o >>= 1) s += __shfl_xor_sync(0xffffffffu, s, o);
        float mean = s * (1.0f / 256.0f);
        float dax = va.x - mean, day = va.y - mean, daz = va.z - mean, daw = va.w - mean;
        float dbx = vb.x - mean, dby = vb.y - mean, dbz = vb.z - mean, dbw = vb.w - mean;
        float vv = dax*dax + day*day + daz*daz + daw*daw
                 + dbx*dbx + dby*dby + dbz*dbz + dbw*dbw;
#pragma unroll
        for (int o = 16; o; o >>= 1) vv += __shfl_xor_sync(0xffffffffu, vv, o);
        float inv = rsqrtf(vv * (1.0f / 256.0f) + 1e-5f);
        float4 na = make_float4(dax*inv*ga.x + ba.x, day*inv*ga.y + ba.y,
                                daz*inv*ga.z + ba.z, daw*inv*ga.w + ba.w);
        float4 nb = make_float4(dbx*inv*gb.x + bb.x, dby*inv*gb.y + bb.y,
                                dbz*inv*gb.z + bb.z, dbw*inv*gb.w + bb.w);
        ((float4*)smx[w * 4 + i])[lane]      = na;
        ((float4*)smx[w * 4 + i])[lane + 32] = nb;
    }
    __syncwarp();

    // GEMM: 128 outputs x 256 channels for 4 positions.
    const float4* Wt4 = (const float4*)g_wt;   // [c][32 float4s of outputs]
    float4 a0 = make_float4(0,0,0,0), a1 = a0, a2 = a0, a3 = a0;
    const float* x0 = smx[w * 4 + 0];
    const float* x1 = smx[w * 4 + 1];
    const float* x2 = smx[w * 4 + 2];
    const float* x3 = smx[w * 4 + 3];
#pragma unroll 4
    for (int c = 0; c < 256; c += 4) {
        float4 w0 = Wt4[(c + 0) * 32 + lane];
        float4 w1 = Wt4[(c + 1) * 32 + lane];
        float4 w2 = Wt4[(c + 2) * 32 + lane];
        float4 w3 = Wt4[(c + 3) * 32 + lane];
        float4 xv;
        xv = *(const float4*)(x0 + c);
        a0.x += w0.x*xv.x + w1.x*xv.y + w2.x*xv.z + w3.x*xv.w;
        a0.y += w0.y*xv.x + w1.y*xv.y + w2.y*xv.z + w3.y*xv.w;
        a0.z += w0.z*xv.x + w1.z*xv.y + w2.z*xv.z + w3.z*xv.w;
        a0.w += w0.w*xv.x + w1.w*xv.y + w2.w*xv.z + w3.w*xv.w;
        xv = *(const float4*)(x1 + c);
        a1.x += w0.x*xv.x + w1.x*xv.y + w2.x*xv.z + w3.x*xv.w;
        a1.y += w0.y*xv.x + w1.y*xv.y + w2.y*xv.z + w3.y*xv.w;
        a1.z += w0.z*xv.x + w1.z*xv.y + w2.z*xv.z + w3.z*xv.w;
        a1.w += w0.w*xv.x + w1.w*xv.y + w2.w*xv.z + w3.w*xv.w;
        xv = *(const float4*)(x2 + c);
        a2.x += w0.x*xv.x + w1.x*xv.y + w2.x*xv.z + w3.x*xv.w;
        a2.y += w0.y*xv.x + w1.y*xv.y + w2.y*xv.z + w3.y*xv.w;
        a2.z += w0.z*xv.x + w1.z*xv.y + w2.z*xv.z + w3.z*xv.w;
        a2.w += w0.w*xv.x + w1.w*xv.y + w2.w*xv.z + w3.w*xv.w;
        xv = *(const float4*)(x3 + c);
        a3.x += w0.x*xv.x + w1.x*xv.y + w2.x*xv.z + w3.x*xv.w;
        a3.y += w0.y*xv.x + w1.y*xv.y + w2.y*xv.z + w3.y*xv.w;
        a3.z += w0.z*xv.x + w1.z*xv.y + w2.z*xv.z + w3.z*xv.w;
        a3.w += w0.w*xv.x + w1.w*xv.y + w2.w*xv.z + w3.w*xv.w;
    }
    // store: lanes 0-15 -> q (outputs 0-63), lanes 16-31 -> k (outputs 64-127)
    float4* q4 = (float4*)g_q48;
    float4* k4 = (float4*)g_kt;
#pragma unroll
    for (int i = 0; i < 4; i++) {
        size_t pos = pbase + i;
        float4 acc = (i == 0) ? a0 : (i == 1) ? a1 : (i == 2) ? a2 : a3;
        if (lane < 16) q4[pos * 16 + lane]        = acc;
        else           k4[pos * 16 + (lane - 16)] = acc;
    }
}

// ---------------------------------------------------------------------------
// K2: bilinear upsample q48 -> qt (align_corners), float4-vectorized gather
__global__ void k_resize() {
    int idx = blockIdx.x * 256 + threadIdx.x;      // B*N1*16 float4s = 294,912
    int c4 = idx & 15;
    int p = (idx >> 4) % N1_;
    int b = (idx >> 4) / N1_;
    int oy = p / OW_, ox = p % OW_;
    float ys = oy * RESC_;
    float xsf = ox * RESC_;
    int y0 = min(max((int)floorf(ys), 0), H_ - 2);
    int x0 = min(max((int)floorf(xsf), 0), W_ - 2);
    float wy = ys - (float)y0, wx = xsf - (float)x0;
    const float4* base = (const float4*)(g_q48 + (size_t)b * HW_ * HID_);
    float4 v00 = base[((y0    ) * W_ + x0    ) * 16 + c4];
    float4 v01 = base[((y0    ) * W_ + x0 + 1) * 16 + c4];
    float4 v10 = base[((y0 + 1) * W_ + x0    ) * 16 + c4];
    float4 v11 = base[((y0 + 1) * W_ + x0 + 1) * 16 + c4];
    float a = (1.f - wy) * (1.f - wx), bq = (1.f - wy) * wx;
    float c = wy * (1.f - wx), dq = wy * wx;
    float4 r;
    r.x = a * v00.x + bq * v01.x + c * v10.x + dq * v11.x;
    r.y = a * v00.y + bq * v01.y + c * v10.y + dq * v11.y;
    r.z = a * v00.z + bq * v01.z + c * v10.z + dq * v11.z;
    r.w = a * v00.w + bq * v01.w + c * v10.w + dq * v11.w;
    ((float4*)g_qt)[idx] = r;
}

// ---------------------------------------------------------------------------
// K3: offset net stage 1: depthwise 3x3 conv + channel LN(32) + exact GELU.
__global__ void k_off1(const float* __restrict__ dw_w,
                       const float* __restrict__ og, const float* __restrict__ ob) {
    int t = threadIdx.x;
    int ch = t & 31, u = t >> 5;
    int gid = blockIdx.x * 8 + u;        // < 4*9216
    int bg = gid / N1_, p = gid % N1_;
    int b = bg >> 1, g = bg & 1;
    int y = p / OW_, x = p % OW_;
    const float* qb = g_qt + (size_t)b * N1_ * HID_ + g * GC_ + ch;
    float acc = 0.0f;
#pragma unroll
    for (int ky = 0; ky < 3; ky++) {
        int ny = y + ky - 1;
        if (ny < 0 || ny >= OH_) continue;
#pragma unroll
        for (int kx = 0; kx < 3; kx++) {
            int nx = x + kx - 1;
            if (nx < 0 || nx >= OW_) continue;
            acc += qb[(size_t)(ny * OW_ + nx) * HID_] * dw_w[ch * 9 + ky * 3 + kx];
        }
    }
    float s = acc;
#pragma unroll
    for (int o = 16; o; o >>= 1) s += __shfl_xor_sync(0xffffffffu, s, o);
    float mean = s * (1.0f / 32.0f);
    float d = acc - mean;
    float vv = d * d;
#pragma unroll
    for (int o = 16; o; o >>= 1) vv += __shfl_xor_sync(0xffffffffu, vv, o);
    float inv = rsqrtf(vv * (1.0f / 32.0f) + 1e-5f);
    float tn = d * inv * og[ch] + ob[ch];
    float ge = 0.5f * tn * (1.0f + erff(tn * 0.70710678118654752f));
    g_tbuf[(size_t)gid * GC_ + ch] = ge;
}

// ---------------------------------------------------------------------------
// K4: offset net stage 2: 3x3 conv 32->18 + bias + tanh -> per-tap corner
//     data (bilinear weights + packed indices), computed ONCE per tap here
//     (lanes 0-8 in parallel) instead of redundantly in k_attn.
__global__ void k_off2(const float* __restrict__ off_b) {
    __shared__ float pr[8][20];
    int t = threadIdx.x;
    int lane = t & 31, u = t >> 5;
    int gid = blockIdx.x * 8 + u;
    int bg = gid / N1_, p = gid % N1_;
    int y = p / OW_, x = p % OW_;
    const float* tb = g_tbuf + (size_t)bg * N1_ * GC_;
    float in[9];
#pragma unroll
    for (int tap = 0; tap < 9; tap++) {
        int ny = y + tap / 3 - 1, nx = x + tap % 3 - 1;
        bool inb = ((unsigned)ny < OH_) && ((unsigned)nx < OW_);
        in[tap] = inb ? tb[(size_t)(ny * OW_ + nx) * GC_ + lane] : 0.0f;
    }
#pragma unroll
    for (int o = 0; o < 18; o++) {
        float acc = 0.f;
#pragma unroll
        for (int tap = 0; tap < 9; tap++)
            acc += in[tap] * g_owt[(tap * 18 + o) * 32 + lane];
#pragma unroll
        for (int sh = 16; sh; sh >>= 1) acc += __shfl_xor_sync(0xffffffffu, acc, sh);
        if (lane == 0) pr[u][o] = acc + off_b[o];
    }
    __syncwarp();
    if (lane < 9) {
        int ky = lane / 3, kx = lane % 3;
        float py = tanhf(pr[u][2 * lane    ]) * RF_ + (float)(ky - 1) + (float)y;
        float px = tanhf(pr[u][2 * lane + 1]) * RF_ + (float)(kx - 1) + (float)x;
        float yy = py * RESC_, xx = px * RESC_;
        float y0f = floorf(yy), x0f = floorf(xx);
        int y0 = (int)y0f, x0 = (int)x0f;
        float wy = yy - y0f, wx = xx - x0f;
        bool yi0 = (y0 >= 0) & (y0 < H_), yi1 = (y0 + 1 >= 0) & (y0 + 1 < H_);
        bool xi0 = (x0 >= 0) & (x0 < W_), xi1 = (x0 + 1 >= 0) & (x0 + 1 < W_);
        int yc0 = min(max(y0, 0), H_ - 1), yc1 = min(max(y0 + 1, 0), H_ - 1);
        int xc0 = min(max(x0, 0), W_ - 1), xc1 = min(max(x0 + 1, 0), W_ - 1);
        float w00 = (yi0 & xi0) ? (1.f - wy) * (1.f - wx) : 0.f;
        float w01 = (yi0 & xi1) ? (1.f - wy) * wx         : 0.f;
        float w10 = (yi1 & xi0) ? wy * (1.f - wx)         : 0.f;
        float w11 = (yi1 & xi1) ? wy * wx                 : 0.f;
        int i00 = yc0 * W_ + xc0, i01 = yc0 * W_ + xc1;
        int i10 = yc1 * W_ + xc0, i11 = yc1 * W_ + xc1;
        size_t off = ((size_t)bg * NSL_ + lane) * N1_ + p;
        g_tw[off] = make_float4(w00, w01, w10, w11);
        g_ti[off] = make_int2(i00 | (i01 << 16), i10 | (i11 << 16));
    }
}

// ---------------------------------------------------------------------------
// K5: fused grid-sample + attention + output, single pass (online softmax).
//     Corner data precomputed by k_off2; broadcast via shfl per tap.
__global__ void k_attn(const float* __restrict__ rpb, float* __restrict__ out) {
    __shared__ float4 so4[8][32];   // [warp][lane] staging
    int t = threadIdx.x;
    int lane = t & 31, w = t >> 5;
    int bh = blockIdx.x / (N1_ / 8);
    int pt = blockIdx.x % (N1_ / 8);
    int b = bh >> 1, h = bh & 1;
    int p = pt * 8 + w;
    int bg = b * NG_ + h;   // head == group (NH == NG, adjacent reshape)

    float qv = g_qt[((size_t)(b * N1_ + p)) * HID_ + h * C2_ + lane] * SCALE_;

    float4 tw = make_float4(0, 0, 0, 0);
    int2  ti = make_int2(0, 0);
    if (lane < 9) {
        size_t off = ((size_t)bg * NSL_ + lane) * N1_ + p;
        tw = g_tw[off];
        ti = g_ti[off];
    }

    const float*  kb = g_kt + (size_t)b * HW_ * HID_ + h * C2_ + lane;
    const float4* vb = (const float4*)(g_xt + (size_t)b * HW_ * C_ + h * 128) + lane;

    float rpbv[9];
#pragma unroll
    for (int j = 0; j < 9; j++) rpbv[j] = rpb[(h * NSL_ + j) * C2_ + lane];

    float m = -1e30f, ssum = 0.f;
    float ax = 0.f, ay = 0.f, az = 0.f, aw = 0.f;

#pragma unroll
    for (int j = 0; j < 9; j++) {
        float w00 = __shfl_sync(0xffffffffu, tw.x, j);
        float w01 = __shfl_sync(0xffffffffu, tw.y, j);
        float w10 = __shfl_sync(0xffffffffu, tw.z, j);
        float w11 = __shfl_sync(0xffffffffu, tw.w, j);
        int   pi0 = __shfl_sync(0xffffffffu, ti.x, j);
        int   pi1 = __shfl_sync(0xffffffffu, ti.y, j);
        int i00 = pi0 & 0xFFFF, i01 = pi0 >> 16;
        int i10 = pi1 & 0xFFFF, i11 = pi1 >> 16;
        // logit: k gather + rpb + q dot (warp reduce)
        float kv = w00 * kb[(size_t)i00 * HID_] + w01 * kb[(size_t)i01 * HID_]
                 + w10 * kb[(size_t)i10 * HID_] + w11 * kb[(size_t)i11 * HID_]
                 + rpbv[j];
        float pr = qv * kv;
#pragma unroll
        for (int o = 16; o; o >>= 1) pr += __shfl_xor_sync(0xffffffffu, pr, o);
        // online softmax update
        float mn = fmaxf(m, pr);
        float sc = __expf(m - mn);
        float wj = __expf(pr - mn);
        ssum = ssum * sc + wj;
        m = mn;
        // v gather (float4: 4 consecutive channels per lane)
        float4 v00 = vb[(size_t)i00 * 64], v01 = vb[(size_t)i01 * 64];
        float4 v10 = vb[(size_t)i10 * 64], v11 = vb[(size_t)i11 * 64];
        ax = ax * sc + wj * (w00 * v00.x + w01 * v01.x + w10 * v10.x + w11 * v11.x);
        ay = ay * sc + wj * (w00 * v00.y + w01 * v01.y + w10 * v10.y + w11 * v11.y);
        az = az * sc + wj * (w00 * v00.z + w01 * v01.z + w10 * v10.z + w11 * v11.z);
        aw = aw * sc + wj * (w00 * v00.w + w01 * v01.w + w10 * v10.w + w11 * v11.w);
    }
    float invs = 1.0f / ssum;
    so4[w][lane] = make_float4(ax * invs, ay * invs, az * invs, aw * invs);
    __syncthreads();
    // coalesced output: 128 channels x 8 positions, float4 per thread
    const float* sof = (const float*)so4;   // [warp][128ch]
    int ch = t >> 1;
    int pp = (t & 1) * 4;
    float4 o4 = make_float4(sof[(pp + 0) * 128 + ch], sof[(pp + 1) * 128 + ch],
                            sof[(pp + 2) * 128 + ch], sof[(pp + 3) * 128 + ch]);
    *(float4*)(out + ((size_t)(b * C_ + h * 128 + ch)) * N1_ + pt * 8 + pp) = o4;
}

// ---------------------------------------------------------------------------
extern "C" void kernel_launch(void* const* d_in, const int* in_sizes, int n_in,
                              void* d_out, int out_size) {
    const float* x     = (const float*)d_in[0];
    const float* ln_g  = (const float*)d_in[1];
    const float* ln_b  = (const float*)d_in[2];
    const float* Wq    = (const float*)d_in[3];
    const float* Wk    = (const float*)d_in[4];
    const float* dw_w  = (const float*)d_in[5];
    const float* olg   = (const float*)d_in[6];
    const float* olb   = (const float*)d_in[7];
    const float* off_w = (const float*)d_in[8];
    const float* off_b = (const float*)d_in[9];
    const float* rpb   = (const float*)d_in[10];
    float* out = (float*)d_out;

    (void)in_sizes; (void)n_in; (void)out_size;

    k_transpose<<<dim3(HW_ / 32, C_ / 32, B_), dim3(32, 8)>>>(x);
    k_wprep<<<(256 * 128 + 18 * 32 * 9 + 255) / 256, 256>>>(Wq, Wk, off_w);
    k_ln_qk<<<B_ * HW_ / 32, 256>>>(ln_g, ln_b);
    k_resize<<<(B_ * N1_ * 16) / 256, 256>>>();
    k_off1<<<(B_ * NG_ * N1_) / 8, 256>>>(dw_w, olg, olb);
    k_off2<<<(B_ * NG_ * N1_) / 8, 256>>>(off_b);
    k_attn<<<(B_ * NH_ * N1_) / 8, 256>>>(rpb, out);
}